// round 4
// baseline (speedup 1.0000x reference)
#include <cuda_runtime.h>
#include <math.h>
#include <stdint.h>

// ---------------- problem dims ----------------
#define BATCH 16384
#define D_IN  1024
#define H_DIM 2048
#define O_DIM 2
#define DW (D_IN / 32)    // 32
#define HW (H_DIM / 32)   // 64

#define LDK 144           // padded smem row pitch (bytes); 144 = 16*9, 16B-aligned

// ---------------- device scratch (no allocs allowed) ----------------
__device__ unsigned g_actA[BATCH * HW];    // packed-T acts (also packed x [32][BATCH])
__device__ unsigned g_actB[BATCH * HW];
__device__ unsigned g_w1T [DW * H_DIM];    // [32][2048] word-major
__device__ unsigned g_w2T [HW * H_DIM];
__device__ unsigned g_w3T [HW * H_DIM];
__device__ unsigned g_woutb[O_DIM * HW];
__device__ float    g_thr [3 * H_DIM];

// ---------------- small kernels ----------------
__global__ void compute_thr_kernel(const float* __restrict__ g, const float* __restrict__ b,
                                   const float* __restrict__ m, const float* __restrict__ v,
                                   float* __restrict__ thr)
{
    int i = blockIdx.x * blockDim.x + threadIdx.x;
    if (i < H_DIM) thr[i] = m[i] - b[i] * sqrtf(v[i] + 1e-5f) / g[i];
}

// pack transposed: src[rows][cwords*32] -> dst[cwords][rows], bit = (src < cmp)
__global__ void pack_bits_T(const float* __restrict__ src, unsigned* __restrict__ dst,
                            int rows, int cwords, float cmp)
{
    int gid = blockIdx.x * blockDim.x + threadIdx.x;
    int w = gid >> 5;
    if (w >= rows * cwords) return;
    int lane = gid & 31;
    int r = w / cwords, wd = w % cwords;
    float v = src[(size_t)r * cwords * 32 + wd * 32 + lane];
    unsigned msk = __ballot_sync(0xffffffffu, v < cmp);
    if (lane == 0) dst[(size_t)wd * rows + r] = msk;
}

__global__ void pack_bits_plain(const float* __restrict__ src, unsigned* __restrict__ dst,
                                int nwords, float cmp)
{
    int gid = blockIdx.x * blockDim.x + threadIdx.x;
    int w = gid >> 5;
    if (w >= nwords) return;
    int lane = gid & 31;
    float v = src[(size_t)w * 32 + lane];
    unsigned msk = __ballot_sync(0xffffffffu, v < cmp);
    if (lane == 0) dst[w] = msk;
}

// ---------------- bit word -> 32 s8 (+1 / -1) ----------------
__device__ __forceinline__ void expand_word_s8(unsigned w, unsigned char* dst)
{
    unsigned q[8];
    #pragma unroll
    for (int v = 0; v < 8; ++v) {
        unsigned n = (w >> (4 * v)) & 0xFu;
        unsigned spread = (n * 0x00204081u) & 0x01010101u;  // bit j -> byte j
        q[v] = 0x01010101u ^ (spread * 0xFEu);              // 0x01 or 0xFF per byte
    }
    ((uint4*)dst)[0] = make_uint4(q[0], q[1], q[2], q[3]);
    ((uint4*)dst)[1] = make_uint4(q[4], q[5], q[6], q[7]);
}

// expand one 128-byte K-chunk of A and B into smem (all 256 threads)
__device__ __forceinline__ void expand_chunk(const unsigned* __restrict__ ApkT,
                                             const unsigned* __restrict__ WpkT,
                                             unsigned char* A, unsigned char* B,
                                             int r0, int c0, int kw0, int tid)
{
    const int row = tid >> 1;
    const int w0  = (tid & 1) * 2;
    #pragma unroll
    for (int t = 0; t < 2; ++t) {
        int wl = w0 + t;
        unsigned aw = ApkT[(size_t)(kw0 + wl) * BATCH + r0 + row];
        expand_word_s8(aw, A + row * LDK + wl * 32);
        unsigned bw = WpkT[(size_t)(kw0 + wl) * H_DIM + c0 + row];
        expand_word_s8(bw, B + row * LDK + wl * 32);
    }
}

// ---------------- int8 mma.sync GEMM + BN-threshold + repack ----------------
// A packed-T [KWORDS][BATCH], W packed-T [KWORDS][H_DIM]; OutT packed [H_DIM/32][BATCH]
template <int KWORDS>
__global__ __launch_bounds__(256, 2)
void bgemm_imma(const unsigned* __restrict__ ApkT,
                const unsigned* __restrict__ WpkT,
                const float*    __restrict__ thr,
                unsigned*       __restrict__ OutT)
{
    extern __shared__ unsigned char smem[];  // [2 bufs][A 128*LDK | B 128*LDK]
    const int tid  = threadIdx.x;
    const int lane = tid & 31;
    const int wid  = tid >> 5;
    const int warpM = wid & 1;    // 0..1 -> 64-row slab
    const int warpN = wid >> 1;   // 0..3 -> 32-col slab
    const int r0 = blockIdx.x * 128;
    const int c0 = blockIdx.y * 128;
    const int NCH = KWORDS / 4;   // 128-byte K chunks

    int acc[4][4][4];
    #pragma unroll
    for (int i = 0; i < 4; ++i)
        #pragma unroll
        for (int j = 0; j < 4; ++j)
            #pragma unroll
            for (int k = 0; k < 4; ++k) acc[i][j][k] = 0;

    expand_chunk(ApkT, WpkT, smem, smem + 128 * LDK, r0, c0, 0, tid);
    __syncthreads();

    for (int c = 0; c < NCH; ++c) {
        const int b = c & 1;
        unsigned char* A = smem + (size_t)b * (2 * 128 * LDK);
        unsigned char* B = A + 128 * LDK;

        #pragma unroll
        for (int s = 0; s < 4; ++s) {
            unsigned afr[4][4];
            #pragma unroll
            for (int i = 0; i < 4; ++i) {
                const unsigned char* ab = A + (warpM * 64 + i * 16 + (lane >> 2)) * LDK
                                            + s * 32 + (lane & 3) * 4;
                afr[i][0] = *(const unsigned*)(ab);
                afr[i][1] = *(const unsigned*)(ab + 8 * LDK);
                afr[i][2] = *(const unsigned*)(ab + 16);
                afr[i][3] = *(const unsigned*)(ab + 8 * LDK + 16);
            }
            #pragma unroll
            for (int j = 0; j < 4; ++j) {
                const unsigned char* bb = B + (warpN * 32 + j * 8 + (lane >> 2)) * LDK
                                            + s * 32 + (lane & 3) * 4;
                unsigned bfr0 = *(const unsigned*)(bb);
                unsigned bfr1 = *(const unsigned*)(bb + 16);
                #pragma unroll
                for (int i = 0; i < 4; ++i) {
                    asm volatile(
                        "mma.sync.aligned.m16n8k32.row.col.s32.s8.s8.s32 "
                        "{%0,%1,%2,%3}, {%4,%5,%6,%7}, {%8,%9}, {%0,%1,%2,%3};"
                        : "+r"(acc[i][j][0]), "+r"(acc[i][j][1]),
                          "+r"(acc[i][j][2]), "+r"(acc[i][j][3])
                        : "r"(afr[i][0]), "r"(afr[i][1]), "r"(afr[i][2]), "r"(afr[i][3]),
                          "r"(bfr0), "r"(bfr1));
                }
            }
        }
        if (c + 1 < NCH) {
            const int nb = b ^ 1;
            unsigned char* An = smem + (size_t)nb * (2 * 128 * LDK);
            expand_chunk(ApkT, WpkT, An, An + 128 * LDK, r0, c0, (c + 1) * 4, tid);
        }
        __syncthreads();
    }

    // ---- epilogue: BN threshold + bit repack (buf0 region is free) ----
    unsigned* pack = (unsigned*)smem;     // 512 words: [row 0..127][word 0..3]
    pack[tid] = 0;
    pack[tid + 256] = 0;

    float t[8];
    #pragma unroll
    for (int j = 0; j < 4; ++j) {
        t[j * 2 + 0] = thr[c0 + warpN * 32 + j * 8 + 2 * (lane & 3) + 0];
        t[j * 2 + 1] = thr[c0 + warpN * 32 + j * 8 + 2 * (lane & 3) + 1];
    }
    __syncthreads();

    #pragma unroll
    for (int i = 0; i < 4; ++i) {
        unsigned mlo = 0, mhi = 0;
        #pragma unroll
        for (int j = 0; j < 4; ++j) {
            int bp = j * 8 + 2 * (lane & 3);
            if ((float)acc[i][j][0] < t[j * 2 + 0]) mlo |= 1u << bp;
            if ((float)acc[i][j][1] < t[j * 2 + 1]) mlo |= 1u << (bp + 1);
            if ((float)acc[i][j][2] < t[j * 2 + 0]) mhi |= 1u << bp;
            if ((float)acc[i][j][3] < t[j * 2 + 1]) mhi |= 1u << (bp + 1);
        }
        int rlo = warpM * 64 + i * 16 + (lane >> 2);
        atomicOr(&pack[rlo * 4 + warpN], mlo);
        atomicOr(&pack[(rlo + 8) * 4 + warpN], mhi);
    }
    __syncthreads();

    #pragma unroll
    for (int k = 0; k < 2; ++k) {
        int idx = tid + k * 256;
        int row = idx & 127, w = idx >> 7;
        OutT[(size_t)((c0 >> 5) + w) * BATCH + r0 + row] = pack[row * 4 + w];
    }
}

// ---------------- final layer: out[B][2] from packed-T acts ----------------
__global__ __launch_bounds__(128)
void final_layer_kernel(const unsigned* __restrict__ AT,   // [HW][BATCH]
                        const unsigned* __restrict__ Wb,   // [2][HW]
                        float* __restrict__ out)
{
    __shared__ unsigned sw[2 * HW];
    if (threadIdx.x < 2 * HW) sw[threadIdx.x] = Wb[threadIdx.x];
    __syncthreads();

    int row = blockIdx.x * blockDim.x + threadIdx.x;
    int a0 = 0, a1 = 0;
    #pragma unroll
    for (int k = 0; k < HW; ++k) {
        unsigned a = AT[(size_t)k * BATCH + row];
        a0 += __popc(a ^ sw[k]);
        a1 += __popc(a ^ sw[HW + k]);
    }
    out[row * 2 + 0] = (float)(H_DIM - 2 * a0);
    out[row * 2 + 1] = (float)(H_DIM - 2 * a1);
}

// ----------------------------------------------------------------------------
extern "C" void kernel_launch(void* const* d_in, const int* in_sizes, int n_in,
                              void* d_out, int out_size)
{
    const float* x    = (const float*)d_in[0];
    const float* w1   = (const float*)d_in[1];
    const float* g1   = (const float*)d_in[2];
    const float* b1   = (const float*)d_in[3];
    const float* m1   = (const float*)d_in[4];
    const float* v1   = (const float*)d_in[5];
    const float* w2   = (const float*)d_in[6];
    const float* g2   = (const float*)d_in[7];
    const float* b2   = (const float*)d_in[8];
    const float* m2   = (const float*)d_in[9];
    const float* v2   = (const float*)d_in[10];
    const float* w3   = (const float*)d_in[11];
    const float* g3   = (const float*)d_in[12];
    const float* b3   = (const float*)d_in[13];
    const float* m3   = (const float*)d_in[14];
    const float* v3   = (const float*)d_in[15];
    const float* wout = (const float*)d_in[16];
    float* out = (float*)d_out;

    unsigned *actA, *actB, *w1T, *w2T, *w3T, *woutb;
    float* thr;
    cudaGetSymbolAddress((void**)&actA,  g_actA);
    cudaGetSymbolAddress((void**)&actB,  g_actB);
    cudaGetSymbolAddress((void**)&w1T,   g_w1T);
    cudaGetSymbolAddress((void**)&w2T,   g_w2T);
    cudaGetSymbolAddress((void**)&w3T,   g_w3T);
    cudaGetSymbolAddress((void**)&woutb, g_woutb);
    cudaGetSymbolAddress((void**)&thr,   g_thr);

    compute_thr_kernel<<<(H_DIM + 255) / 256, 256>>>(g1, b1, m1, v1, thr);
    compute_thr_kernel<<<(H_DIM + 255) / 256, 256>>>(g2, b2, m2, v2, thr + H_DIM);
    compute_thr_kernel<<<(H_DIM + 255) / 256, 256>>>(g3, b3, m3, v3, thr + 2 * H_DIM);

    // pack x (act = binq(2x-1) -> bit = x < 0.5) and weights (bit = w < 0), transposed
    {
        long nw = (long)BATCH * DW;
        pack_bits_T<<<(unsigned)((nw * 32 + 255) / 256), 256>>>(x, actA, BATCH, DW, 0.5f);
        nw = (long)H_DIM * DW;
        pack_bits_T<<<(unsigned)((nw * 32 + 255) / 256), 256>>>(w1, w1T, H_DIM, DW, 0.0f);
        nw = (long)H_DIM * HW;
        pack_bits_T<<<(unsigned)((nw * 32 + 255) / 256), 256>>>(w2, w2T, H_DIM, HW, 0.0f);
        pack_bits_T<<<(unsigned)((nw * 32 + 255) / 256), 256>>>(w3, w3T, H_DIM, HW, 0.0f);
        pack_bits_plain<<<(O_DIM * HW * 32 + 255) / 256, 256>>>(wout, woutb, O_DIM * HW, 0.0f);
    }

    const int SMEM_BYTES = 4 * 128 * LDK;   // 73728
    cudaFuncSetAttribute(bgemm_imma<DW>, cudaFuncAttributeMaxDynamicSharedMemorySize, SMEM_BYTES);
    cudaFuncSetAttribute(bgemm_imma<HW>, cudaFuncAttributeMaxDynamicSharedMemorySize, SMEM_BYTES);

    dim3 grid(BATCH / 128, H_DIM / 128);
    bgemm_imma<DW><<<grid, 256, SMEM_BYTES>>>(actA, w1T, thr,              actB);
    bgemm_imma<HW><<<grid, 256, SMEM_BYTES>>>(actB, w2T, thr + H_DIM,      actA);
    bgemm_imma<HW><<<grid, 256, SMEM_BYTES>>>(actA, w3T, thr + 2 * H_DIM,  actB);

    final_layer_kernel<<<BATCH / 128, 128>>>(actB, woutb, out);
}

// round 5
// speedup vs baseline: 2.8544x; 2.8544x over previous
#include <cuda_runtime.h>
#include <math.h>
#include <stdint.h>

// ---------------- problem dims ----------------
#define BATCH 16384
#define D_IN  1024
#define H_DIM 2048
#define O_DIM 2
#define DW (D_IN / 32)    // 32
#define HW (H_DIM / 32)   // 64

// ---------------- device scratch (no allocs allowed) ----------------
__device__ unsigned g_actA[BATCH * HW];    // packed-T acts (also packed x: [DW][BATCH])
__device__ unsigned g_actB[BATCH * HW];
__device__ unsigned g_w1T [DW * H_DIM];    // [DW][2048] k-major
__device__ unsigned g_w2T [HW * H_DIM];
__device__ unsigned g_w3T [HW * H_DIM];
__device__ unsigned g_woutb[O_DIM * HW];
__device__ float    g_thr [3 * H_DIM];

// ---------------- LOP3 helpers (single-instruction 3-input xor / majority) ----------------
__device__ __forceinline__ unsigned xor3(unsigned a, unsigned b, unsigned c) {
    unsigned r;
    asm("lop3.b32 %0, %1, %2, %3, 0x96;" : "=r"(r) : "r"(a), "r"(b), "r"(c));
    return r;
}
__device__ __forceinline__ unsigned maj3(unsigned a, unsigned b, unsigned c) {
    unsigned r;
    asm("lop3.b32 %0, %1, %2, %3, 0xE8;" : "=r"(r) : "r"(a), "r"(b), "r"(c));
    return r;
}

// ---------------- small kernels ----------------
__global__ void compute_thr_kernel(const float* __restrict__ g, const float* __restrict__ b,
                                   const float* __restrict__ m, const float* __restrict__ v,
                                   float* __restrict__ thr)
{
    int i = blockIdx.x * blockDim.x + threadIdx.x;
    if (i < H_DIM) thr[i] = m[i] - b[i] * sqrtf(v[i] + 1e-5f) / g[i];
}

// vectorized transposed pack: src[rows][cwords*32] -> dst[cwords][rows], bit = (src < cmp)
// one warp handles one row x 4 words (128 floats) via float4 + shfl-OR.
__global__ void pack_bits_T4(const float4* __restrict__ src, unsigned* __restrict__ dst,
                             int rows, int cwords, float cmp)
{
    int gid  = blockIdx.x * blockDim.x + threadIdx.x;
    int wrp  = gid >> 5;
    int lane = gid & 31;
    int wq   = cwords >> 2;           // 4-word groups per row
    if (wrp >= rows * wq) return;
    int row = wrp / wq, w0 = (wrp % wq) * 4;

    float4 f = src[(size_t)row * (cwords * 8) + w0 * 8 + lane];  // cwords*32/4 float4 per row
    unsigned nib = (f.x < cmp ? 1u : 0u) | (f.y < cmp ? 2u : 0u)
                 | (f.z < cmp ? 4u : 0u) | (f.w < cmp ? 8u : 0u);
    unsigned v = nib << ((lane & 7) * 4);
    v |= __shfl_xor_sync(0xffffffffu, v, 1);
    v |= __shfl_xor_sync(0xffffffffu, v, 2);
    v |= __shfl_xor_sync(0xffffffffu, v, 4);
    if ((lane & 7) == 0)
        dst[(size_t)(w0 + (lane >> 3)) * rows + row] = v;
}

__global__ void pack_bits_plain(const float* __restrict__ src, unsigned* __restrict__ dst,
                                int nwords, float cmp)
{
    int gid = blockIdx.x * blockDim.x + threadIdx.x;
    int w = gid >> 5;
    if (w >= nwords) return;
    int lane = gid & 31;
    float v = src[(size_t)w * 32 + lane];
    unsigned msk = __ballot_sync(0xffffffffu, v < cmp);
    if (lane == 0) dst[w] = msk;
}

// ---------------- CSA-popc binary GEMM + BN-threshold + repack ----------------
// CTA tile 64 rows x 64 cols, 256 threads = 8 warps (4 row-groups x 2 col-groups).
// Warp: 16 rows x 32 cols. Lane: rows warpM*16+(l>>3)*4+rr, cols warpN*32+(l&7)+8*jj.
// Inner loop: 8-word K window, 5-CSA tree -> 4 POPCs per 8 words per acc.
template <int KW>
__global__ __launch_bounds__(256, 2)
void bgemm_csa(const unsigned* __restrict__ ApkT,   // [KW][BATCH]
               const unsigned* __restrict__ WpkT,   // [KW][H_DIM]
               const float*    __restrict__ thr,    // [H_DIM]
               unsigned*       __restrict__ OutT)   // [H_DIM/32][BATCH]
{
    __shared__ unsigned sA[64 * KW];
    __shared__ unsigned sW[64 * KW];

    const int tid  = threadIdx.x;
    const int lane = tid & 31;
    const int wid  = tid >> 5;
    const int warpM = wid & 3;
    const int warpN = wid >> 2;
    const int r0 = blockIdx.x * 64;
    const int c0 = blockIdx.y * 64;

    // fill sA: word (row,k) at row*KW + ((k4 ^ ((row>>2)&7))<<2 | kk)
    #pragma unroll 4
    for (int idx = tid; idx < 64 * KW; idx += 256) {
        int k = idx >> 6, row = idx & 63;
        sA[row * KW + ((((k >> 2) ^ ((row >> 2) & 7)) << 2) | (k & 3))] =
            ApkT[(size_t)k * BATCH + r0 + row];
    }
    // fill sW: word (col,k) at col*KW + ((k4 ^ (col&7))<<2 | kk)
    #pragma unroll 4
    for (int idx = tid; idx < 64 * KW; idx += 256) {
        int k = idx >> 6, col = idx & 63;
        sW[col * KW + ((((k >> 2) ^ (col & 7)) << 2) | (k & 3))] =
            WpkT[(size_t)k * H_DIM + c0 + col];
    }
    __syncthreads();

    int acc[4][4];
    #pragma unroll
    for (int r = 0; r < 4; ++r)
        #pragma unroll
        for (int j = 0; j < 4; ++j) acc[r][j] = 0;

    const int rbase = warpM * 16 + (lane >> 3) * 4;
    const int l7 = lane & 7;

    #pragma unroll
    for (int k8 = 0; k8 < KW / 8; ++k8) {
        uint4 a[4][2], b[4][2];
        #pragma unroll
        for (int rr = 0; rr < 4; ++rr) {
            int row = rbase + rr;
            const unsigned* p = sA + row * KW;
            #pragma unroll
            for (int h = 0; h < 2; ++h) {
                int k4 = 2 * k8 + h;
                a[rr][h] = *(const uint4*)(p + ((k4 ^ ((row >> 2) & 7)) << 2));
            }
        }
        #pragma unroll
        for (int jj = 0; jj < 4; ++jj) {
            int col = warpN * 32 + l7 + 8 * jj;
            const unsigned* p = sW + col * KW;
            #pragma unroll
            for (int h = 0; h < 2; ++h) {
                int k4 = 2 * k8 + h;
                b[jj][h] = *(const uint4*)(p + ((k4 ^ l7) << 2));
            }
        }
        #pragma unroll
        for (int rr = 0; rr < 4; ++rr) {
            #pragma unroll
            for (int jj = 0; jj < 4; ++jj) {
                unsigned x0 = a[rr][0].x ^ b[jj][0].x;
                unsigned x1 = a[rr][0].y ^ b[jj][0].y;
                unsigned x2 = a[rr][0].z ^ b[jj][0].z;
                unsigned x3 = a[rr][0].w ^ b[jj][0].w;
                unsigned x4 = a[rr][1].x ^ b[jj][1].x;
                unsigned x5 = a[rr][1].y ^ b[jj][1].y;
                unsigned x6 = a[rr][1].z ^ b[jj][1].z;
                unsigned x7 = a[rr][1].w ^ b[jj][1].w;
                // 5-CSA tree: popc(x0..x7) with 4 POPCs
                unsigned s1 = xor3(x0, x1, x2), c1 = maj3(x0, x1, x2);
                unsigned s2 = xor3(x3, x4, x5), c2 = maj3(x3, x4, x5);
                unsigned s3 = xor3(s1, s2, x6), c3 = maj3(s1, s2, x6);
                unsigned s4 = xor3(c1, c2, c3), c4 = maj3(c1, c2, c3);
                acc[rr][jj] += __popc(s3) + __popc(x7)
                             + 2 * __popc(s4) + 4 * __popc(c4);
            }
        }
    }

    // ---- epilogue: BN threshold + shfl-OR repack ----
    const int Kbits = KW * 32;
    float t[4];
    #pragma unroll
    for (int jj = 0; jj < 4; ++jj)
        t[jj] = thr[c0 + warpN * 32 + l7 + 8 * jj];

    #pragma unroll
    for (int rr = 0; rr < 4; ++rr) {
        unsigned v = 0;
        #pragma unroll
        for (int jj = 0; jj < 4; ++jj) {
            int C = Kbits - 2 * acc[rr][jj];
            if ((float)C < t[jj]) v |= 1u << (l7 + 8 * jj);
        }
        v |= __shfl_xor_sync(0xffffffffu, v, 1);
        v |= __shfl_xor_sync(0xffffffffu, v, 2);
        v |= __shfl_xor_sync(0xffffffffu, v, 4);
        if (l7 == 0) {
            int row = r0 + rbase + rr;
            OutT[(size_t)((c0 >> 5) + warpN) * BATCH + row] = v;
        }
    }
}

// ---------------- final layer: out[B][2] from packed-T acts ----------------
__global__ __launch_bounds__(128)
void final_layer_kernel(const unsigned* __restrict__ AT,   // [HW][BATCH]
                        const unsigned* __restrict__ Wb,   // [2][HW]
                        float* __restrict__ out)
{
    __shared__ unsigned sw[2 * HW];
    if (threadIdx.x < 2 * HW) sw[threadIdx.x] = Wb[threadIdx.x];
    __syncthreads();

    int row = blockIdx.x * blockDim.x + threadIdx.x;
    int a0 = 0, a1 = 0;
    #pragma unroll
    for (int k = 0; k < HW; ++k) {
        unsigned a = AT[(size_t)k * BATCH + row];
        a0 += __popc(a ^ sw[k]);
        a1 += __popc(a ^ sw[HW + k]);
    }
    out[row * 2 + 0] = (float)(H_DIM - 2 * a0);
    out[row * 2 + 1] = (float)(H_DIM - 2 * a1);
}

// ----------------------------------------------------------------------------
extern "C" void kernel_launch(void* const* d_in, const int* in_sizes, int n_in,
                              void* d_out, int out_size)
{
    const float* x    = (const float*)d_in[0];
    const float* w1   = (const float*)d_in[1];
    const float* g1   = (const float*)d_in[2];
    const float* b1   = (const float*)d_in[3];
    const float* m1   = (const float*)d_in[4];
    const float* v1   = (const float*)d_in[5];
    const float* w2   = (const float*)d_in[6];
    const float* g2   = (const float*)d_in[7];
    const float* b2   = (const float*)d_in[8];
    const float* m2   = (const float*)d_in[9];
    const float* v2   = (const float*)d_in[10];
    const float* w3   = (const float*)d_in[11];
    const float* g3   = (const float*)d_in[12];
    const float* b3   = (const float*)d_in[13];
    const float* m3   = (const float*)d_in[14];
    const float* v3   = (const float*)d_in[15];
    const float* wout = (const float*)d_in[16];
    float* out = (float*)d_out;

    unsigned *actA, *actB, *w1T, *w2T, *w3T, *woutb;
    float* thr;
    cudaGetSymbolAddress((void**)&actA,  g_actA);
    cudaGetSymbolAddress((void**)&actB,  g_actB);
    cudaGetSymbolAddress((void**)&w1T,   g_w1T);
    cudaGetSymbolAddress((void**)&w2T,   g_w2T);
    cudaGetSymbolAddress((void**)&w3T,   g_w3T);
    cudaGetSymbolAddress((void**)&woutb, g_woutb);
    cudaGetSymbolAddress((void**)&thr,   g_thr);

    compute_thr_kernel<<<(H_DIM + 255) / 256, 256>>>(g1, b1, m1, v1, thr);
    compute_thr_kernel<<<(H_DIM + 255) / 256, 256>>>(g2, b2, m2, v2, thr + H_DIM);
    compute_thr_kernel<<<(H_DIM + 255) / 256, 256>>>(g3, b3, m3, v3, thr + 2 * H_DIM);

    // pack x (act = binq(2x-1) -> bit = x < 0.5) and weights (bit = w < 0), transposed
    {
        long nthr = (long)BATCH * (DW / 4) * 32;      // warps = rows*cwords/4
        pack_bits_T4<<<(unsigned)((nthr + 255) / 256), 256>>>((const float4*)x, actA, BATCH, DW, 0.5f);
        nthr = (long)H_DIM * (DW / 4) * 32;
        pack_bits_T4<<<(unsigned)((nthr + 255) / 256), 256>>>((const float4*)w1, w1T, H_DIM, DW, 0.0f);
        nthr = (long)H_DIM * (HW / 4) * 32;
        pack_bits_T4<<<(unsigned)((nthr + 255) / 256), 256>>>((const float4*)w2, w2T, H_DIM, HW, 0.0f);
        pack_bits_T4<<<(unsigned)((nthr + 255) / 256), 256>>>((const float4*)w3, w3T, H_DIM, HW, 0.0f);
        pack_bits_plain<<<(O_DIM * HW * 32 + 255) / 256, 256>>>(wout, woutb, O_DIM * HW, 0.0f);
    }

    dim3 grid(BATCH / 64, H_DIM / 64);
    bgemm_csa<DW><<<grid, 256>>>(actA, w1T, thr,             actB);
    bgemm_csa<HW><<<grid, 256>>>(actB, w2T, thr + H_DIM,     actA);
    bgemm_csa<HW><<<grid, 256>>>(actA, w3T, thr + 2 * H_DIM, actB);

    final_layer_kernel<<<BATCH / 128, 128>>>(actB, woutb, out);
}